// round 2
// baseline (speedup 1.0000x reference)
#include <cuda_runtime.h>
#include <cuda_bf16.h>
#include <math.h>

#define N_PL 16
#define OBJ  10
#define MOBJ 36

// Unordered-pair index tables (j<=k for the 55-list, j<k for the 45-list)
__constant__ unsigned char P55J[55] = {
    0,0,0,0,0,0,0,0,0,0, 1,1,1,1,1,1,1,1,1, 2,2,2,2,2,2,2,2,
    3,3,3,3,3,3,3, 4,4,4,4,4,4, 5,5,5,5,5, 6,6,6,6, 7,7,7, 8,8, 9};
__constant__ unsigned char P55K[55] = {
    0,1,2,3,4,5,6,7,8,9, 1,2,3,4,5,6,7,8,9, 2,3,4,5,6,7,8,9,
    3,4,5,6,7,8,9, 4,5,6,7,8,9, 5,6,7,8,9, 6,7,8,9, 7,8,9, 8,9, 9};
__constant__ unsigned char P45J[45] = {
    0,0,0,0,0,0,0,0,0, 1,1,1,1,1,1,1,1, 2,2,2,2,2,2,2,
    3,3,3,3,3,3, 4,4,4,4,4, 5,5,5,5, 6,6,6, 7,7, 8};
__constant__ unsigned char P45K[45] = {
    1,2,3,4,5,6,7,8,9, 2,3,4,5,6,7,8,9, 3,4,5,6,7,8,9,
    4,5,6,7,8,9, 5,6,7,8,9, 6,7,8,9, 7,8,9, 8,9, 9};
// (j,k) -> strict-pair index; 255 on the diagonal (unused)
__constant__ unsigned char PIDX[100] = {
    255,0,1,2,3,4,5,6,7,8,
    0,255,9,10,11,12,13,14,15,16,
    1,9,255,17,18,19,20,21,22,23,
    2,10,17,255,24,25,26,27,28,29,
    3,11,18,24,255,30,31,32,33,34,
    4,12,19,25,30,255,35,36,37,38,
    5,13,20,26,31,35,255,39,40,41,
    6,14,21,27,32,36,39,255,42,43,
    7,15,22,28,33,37,40,42,255,44,
    8,16,23,29,34,38,41,43,44,255};

// fused plin: tab[i] = (csum[i], w[i+1]); args are guaranteed in [0,1]
__device__ __forceinline__ float plin_f(const float2* __restrict__ tb, float x) {
    float y = x * 16.0f;
    int i = (int)y;                // trunc == floor (x >= 0); x<=1 -> i<=16
    float f = y - (float)i;
    float2 p = tb[i];
    return fmaf(f, p.y, p.x);
}

__global__ __launch_bounds__(96, 16)
void counter_kernel(const float* __restrict__ boxes,      // [n, 4, 36]
                    const float* __restrict__ attention,  // [n, 36]
                    const float* __restrict__ ws,         // [8, 17]
                    float* __restrict__ out,              // [n, 11]
                    int n) {
    __shared__ float2 tab[8][N_PL + 1];
    __shared__ float araw[MOBJ];
    __shared__ float att[OBJ];
    __shared__ float box4[4][OBJ];
    __shared__ float dedup[OBJ][OBJ];
    __shared__ float score55[55];
    __shared__ float pairSim[45];
    __shared__ float invr[OBJ];
    __shared__ float red[3][3];
    __shared__ float bc2[2];

    const int row = blockIdx.x;
    const int t = threadIdx.x;

    // ---- plin tables (threads 0..7) ----
    if (t < 8) {
        float w[N_PL + 1];
        float s = 0.0f;
        #pragma unroll
        for (int i = 0; i <= N_PL; i++) { w[i] = fabsf(ws[t * (N_PL + 1) + i]); s += w[i]; }
        float inv = 1.0f / s;
        float c = 0.0f;
        #pragma unroll
        for (int i = 0; i <= N_PL; i++) {
            float wn = w[i] * inv;
            c += wn;
            w[i] = c;                       // reuse as cumsum
        }
        // need normalized w[i+1] again: recompute from csum diff (exact: csum built from wn adds)
        #pragma unroll
        for (int i = 0; i <= N_PL; i++) {
            float wnext = (i < N_PL) ? fabsf(ws[t * (N_PL + 1) + i + 1]) * inv : 0.0f;
            tab[t][i] = make_float2(w[i], wnext);
        }
    }
    // ---- raw attention loads (threads 40..75, disjoint from table threads) ----
    if (t >= 40 && t < 40 + MOBJ) {
        araw[t - 40] = attention[(size_t)row * MOBJ + (t - 40)];
    }
    __syncthreads();

    // ---- top-10 set via rank count (output invariant to selection order) ----
    if (t < MOBJ) {
        float v = araw[t];
        int r = 0;
        #pragma unroll
        for (int j = 0; j < MOBJ; j++) {
            float aj = araw[j];             // broadcast LDS (uniform address)
            r += (aj > v) || (aj == v && j < t);
        }
        if (r < OBJ) {
            att[r] = 1.0f / (1.0f + expf(-v));
            const float* bp = boxes + (size_t)row * (4 * MOBJ) + t;
            box4[0][r] = bp[0];
            box4[1][r] = bp[MOBJ];
            box4[2][r] = bp[2 * MOBJ];
            box4[3][r] = bp[3 * MOBJ];
        }
    }
    __syncthreads();

    // ---- pairwise (55 unordered pairs j<=k): dist, score, dedup, dconf ----
    float dC = 0.0f;
    if (t < 55) {
        int j = P55J[t], k = P55K[t];
        float ax0 = box4[0][j], ay0 = box4[1][j], ax1 = box4[2][j], ay1 = box4[3][j];
        float bx0 = box4[0][k], by0 = box4[1][k], bx1 = box4[2][k], by1 = box4[3][k];
        float iw = fmaxf(fminf(ax1, bx1) - fmaxf(ax0, bx0), 0.0f);
        float ih = fmaxf(fminf(ay1, by1) - fmaxf(ay0, by0), 0.0f);
        float inter = iw * ih;
        float aa = fmaxf(ax1 - ax0, 0.0f) * fmaxf(ay1 - ay0, 0.0f);
        float ab = fmaxf(bx1 - bx0, 0.0f) * fmaxf(by1 - by0, 0.0f);
        float d = 1.0f - inter / (aa + ab - inter + 1e-12f);
        float rel = att[j] * att[k];
        score55[t] = plin_f(tab[0], rel) * plin_f(tab[1], d);
        float dd = plin_f(tab[3], rel) * plin_f(tab[4], d);
        dedup[j][k] = dd;
        dedup[k][j] = dd;
        float wgt = (j == k) ? 1.0f : 2.0f;
        dC = wgt * fabsf(plin_f(tab[6], d) - 0.5f);
    }
    __syncthreads();

    // ---- sim for 45 strict pairs, each split across 2 threads (halves of i) ----
    {
        int p = t >> 1; if (p > 44) p = 44;   // lanes 90..95 compute a clone (no write)
        int h = t & 1;
        int j = P45J[p], k = P45K[p];
        int i0 = h * 5;
        float prod = 1.0f;
        #pragma unroll
        for (int i = 0; i < 5; i++) {
            float diff = fabsf(dedup[i0 + i][j] - dedup[i0 + i][k]);
            prod *= plin_f(tab[2], 1.0f - diff);
        }
        if (h == 0) prod *= plin_f(tab[2], 1.0f - fabsf(att[j] - att[k]));
        float other = __shfl_xor_sync(0xffffffffu, prod, 1);
        prod *= other;
        if (h == 0 && t < 90) pairSim[p] = prod;
    }
    __syncthreads();

    // ---- row_sims (diag sim == 1.0 exactly) and reciprocal ----
    if (t < OBJ) {
        float s = 1.0f;
        #pragma unroll
        for (int k = 0; k < OBJ; k++) {
            unsigned idx = PIDX[t * OBJ + k];
            if (idx != 255u) s += pairSim[idx];
        }
        invr[t] = 1.0f / s;
    }
    __syncthreads();

    // ---- partial sums ----
    float sT = 0.0f, aC = 0.0f;
    if (t < 55) {
        int j = P55J[t], k = P55K[t];
        float wgt = (j == k) ? 1.0f : 2.0f;
        sT = wgt * score55[t] * invr[j] * invr[k];
    }
    if (t < OBJ) {
        float a = att[t];
        sT += plin_f(tab[0], a * a) * invr[t];
        aC = fabsf(plin_f(tab[5], a) - 0.5f);
    }

    // ---- block reduction (3 warps) ----
    #pragma unroll
    for (int o = 16; o > 0; o >>= 1) {
        sT += __shfl_down_sync(0xffffffffu, sT, o);
        aC += __shfl_down_sync(0xffffffffu, aC, o);
        dC += __shfl_down_sync(0xffffffffu, dC, o);
    }
    int w = t >> 5, l = t & 31;
    if (l == 0) { red[w][0] = sT; red[w][1] = aC; red[w][2] = dC; }
    __syncthreads();

    if (t == 0) {
        float S1 = red[0][0] + red[1][0] + red[2][0];
        float S2 = red[0][1] + red[1][1] + red[2][1];
        float S3 = red[0][2] + red[1][2] + red[2][2];
        bc2[0] = sqrtf(S1 + 1e-20f);
        bc2[1] = plin_f(tab[7], S2 * 0.1f + S3 * 0.01f);
    }
    __syncthreads();

    // ---- one_hot * conf ----
    if (t < OBJ + 1) {
        float total = bc2[0], conf = bc2[1];
        float s = fminf(fmaxf(total, 0.0f), (float)OBJ);
        int i = (int)s;
        float f = s - truncf(s);
        int il = i < OBJ ? i : OBJ;
        int ir = (i + 1) < OBJ ? (i + 1) : OBJ;
        float v = (1.0f - f) * (t == il ? 1.0f : 0.0f) + f * (t == ir ? 1.0f : 0.0f);
        out[(size_t)row * (OBJ + 1) + t] = v * conf;
    }
}

extern "C" void kernel_launch(void* const* d_in, const int* in_sizes, int n_in,
                              void* d_out, int out_size) {
    const float* boxes     = (const float*)d_in[0];
    const float* attention = (const float*)d_in[1];
    const float* ws        = (const float*)d_in[2];
    float* out = (float*)d_out;
    int n = in_sizes[1] / MOBJ;
    counter_kernel<<<n, 96>>>(boxes, attention, ws, out, n);
}

// round 3
// speedup vs baseline: 1.5303x; 1.5303x over previous
#include <cuda_runtime.h>
#include <cuda_bf16.h>
#include <math.h>

#define N_PL 16
#define OBJ  10
#define MOBJ 36

// fused plin: tab[i] = (csum[i], w_norm[i+1]); arguments guaranteed in [0,1]
__device__ __forceinline__ float plin_f(const float2* __restrict__ tb, float x) {
    float y = x * 16.0f;
    int i = (int)y;                 // trunc == floor (x >= 0); x<=1 -> i<=16, f=0 at 16
    float f = y - (float)i;
    float2 p = tb[i];
    return fmaf(f, p.y, p.x);
}

// Inverse triangular index, j<=k list over 10 objects (55 pairs).
// base(j) = j*(21-j)/2. Closed form + exact integer correction (fast-math safe).
__device__ __forceinline__ void pair55(int p, int& j, int& k) {
    int jj = (int)(10.5f - sqrtf(110.25f - 2.0f * (float)p));
    jj = max(0, min(9, jj));
    int base = (jj * (21 - jj)) >> 1;
    if (p < base) { jj--; base = (jj * (21 - jj)) >> 1; }
    else {
        int nbase = ((jj + 1) * (20 - jj)) >> 1;
        if (p >= nbase) { jj++; base = nbase; }
    }
    j = jj; k = jj + (p - base);
}

// Inverse triangular index, j<k list over 10 objects (45 pairs).
// base(j) = j*(19-j)/2.
__device__ __forceinline__ void pair45(int p, int& j, int& k) {
    int jj = (int)(9.5f - sqrtf(90.25f - 2.0f * (float)p));
    jj = max(0, min(8, jj));
    int base = (jj * (19 - jj)) >> 1;
    if (p < base) { jj--; base = (jj * (19 - jj)) >> 1; }
    else {
        int nbase = ((jj + 1) * (18 - jj)) >> 1;
        if (p >= nbase) { jj++; base = nbase; }
    }
    j = jj; k = jj + 1 + (p - base);
}

__global__ __launch_bounds__(128, 12)
void counter_kernel(const float* __restrict__ boxes,      // [n, 4, 36]
                    const float* __restrict__ attention,  // [n, 36]
                    const float* __restrict__ ws,         // [8, 17]
                    float* __restrict__ out,              // [n, 11]
                    int n) {
    __shared__ float2 tab[8][N_PL + 1];
    __shared__ float araw[MOBJ];
    __shared__ float att[OBJ];
    __shared__ float box4[4][OBJ];
    __shared__ float dedup[OBJ][OBJ];
    __shared__ float simM[OBJ][OBJ];
    __shared__ float score55[55];
    __shared__ float invr[OBJ];
    __shared__ float red[4][3];
    __shared__ float bc2[2];

    const int row = blockIdx.x;
    const int t = threadIdx.x;

    // Per-thread pair indices, computed once in registers (no memory gathers)
    int j55, k55;  pair55(t < 55 ? t : 54, j55, k55);
    const float wgt = (j55 == k55) ? 1.0f : 2.0f;
    int p45 = t >> 1; if (p45 > 44) p45 = 44;
    const int h45 = t & 1;
    int j45, k45;  pair45(p45, j45, k45);

    // ---- raw attention loads (threads 0..35) ----
    float myv = 0.0f;
    if (t < MOBJ) {
        myv = attention[(size_t)row * MOBJ + t];
        araw[t] = myv;
    }
    // ---- plin tables (threads 64..71, overlap with loads) ----
    if (t >= 64 && t < 72) {
        const int r = t - 64;
        float w[N_PL + 1];
        float s = 0.0f;
        #pragma unroll
        for (int i = 0; i <= N_PL; i++) { w[i] = fabsf(ws[r * (N_PL + 1) + i]); s += w[i]; }
        float inv = 1.0f / s;
        float c = 0.0f;
        #pragma unroll
        for (int i = 0; i <= N_PL; i++) {
            c += w[i] * inv;
            float wnext = (i < N_PL) ? w[i + 1] * inv : 0.0f;
            tab[r][i] = make_float2(c, wnext);
        }
    }
    __syncthreads();

    // ---- top-10 set via rank count (output invariant to selection order) ----
    if (t < MOBJ) {
        int r = 0;
        #pragma unroll
        for (int j = 0; j < MOBJ; j++) {
            float aj = araw[j];             // uniform-address broadcast LDS
            r += (aj > myv) || (aj == myv && j < t);
        }
        if (r < OBJ) {
            att[r] = 1.0f / (1.0f + expf(-myv));
            const float* bp = boxes + (size_t)row * (4 * MOBJ) + t;
            box4[0][r] = bp[0];
            box4[1][r] = bp[MOBJ];
            box4[2][r] = bp[2 * MOBJ];
            box4[3][r] = bp[3 * MOBJ];
        }
    }
    __syncthreads();

    // ---- pairwise (55 unordered pairs j<=k): dist, score, dedup, dconf ----
    float dC = 0.0f;
    if (t < 55) {
        const int j = j55, k = k55;
        float ax0 = box4[0][j], ay0 = box4[1][j], ax1 = box4[2][j], ay1 = box4[3][j];
        float bx0 = box4[0][k], by0 = box4[1][k], bx1 = box4[2][k], by1 = box4[3][k];
        float iw = fmaxf(fminf(ax1, bx1) - fmaxf(ax0, bx0), 0.0f);
        float ih = fmaxf(fminf(ay1, by1) - fmaxf(ay0, by0), 0.0f);
        float inter = iw * ih;
        float aa = fmaxf(ax1 - ax0, 0.0f) * fmaxf(ay1 - ay0, 0.0f);
        float ab = fmaxf(bx1 - bx0, 0.0f) * fmaxf(by1 - by0, 0.0f);
        float d = 1.0f - inter / (aa + ab - inter + 1e-12f);
        float rel = att[j] * att[k];
        score55[t] = plin_f(tab[0], rel) * plin_f(tab[1], d);
        float dd = plin_f(tab[3], rel) * plin_f(tab[4], d);
        dedup[j][k] = dd;
        dedup[k][j] = dd;
        dC = wgt * fabsf(plin_f(tab[6], d) - 0.5f);
    }
    __syncthreads();

    // ---- sim: 45 strict pairs x 2 threads (5 inner-i each), shfl combine ----
    {
        const int j = j45, k = k45;
        const int i0 = h45 * 5;
        float prod = 1.0f;
        #pragma unroll
        for (int i = 0; i < 5; i++) {
            float diff = fabsf(dedup[i0 + i][j] - dedup[i0 + i][k]);
            prod *= plin_f(tab[2], 1.0f - diff);
        }
        if (h45 == 0) prod *= plin_f(tab[2], 1.0f - fabsf(att[j] - att[k]));
        prod *= __shfl_xor_sync(0xffffffffu, prod, 1);
        if (h45 == 0 && t < 90) { simM[j][k] = prod; simM[k][j] = prod; }
        if (t >= 96 && t < 96 + OBJ) simM[t - 96][t - 96] = 1.0f;  // diag (exact)
    }
    __syncthreads();

    // ---- row_sims reciprocal (conflict-free: banks 10t+k distinct over t) ----
    if (t < OBJ) {
        float s = 0.0f;
        #pragma unroll
        for (int k = 0; k < OBJ; k++) s += simM[t][k];
        invr[t] = 1.0f / s;
    }
    __syncthreads();

    // ---- partial sums (warps 0-1: score; warp 2: correction + att_conf) ----
    float sT = 0.0f, aC = 0.0f;
    if (t < 55) {
        sT = wgt * score55[t] * invr[j55] * invr[k55];
    }
    if (t >= 64 && t < 64 + OBJ) {
        const int q = t - 64;
        float a = att[q];
        sT = plin_f(tab[0], a * a) * invr[q];
        aC = fabsf(plin_f(tab[5], a) - 0.5f);
    }

    // ---- block reduction (4 warps) ----
    #pragma unroll
    for (int o = 16; o > 0; o >>= 1) {
        sT += __shfl_down_sync(0xffffffffu, sT, o);
        aC += __shfl_down_sync(0xffffffffu, aC, o);
        dC += __shfl_down_sync(0xffffffffu, dC, o);
    }
    const int w = t >> 5, l = t & 31;
    if (l == 0) { red[w][0] = sT; red[w][1] = aC; red[w][2] = dC; }
    __syncthreads();

    if (t == 0) {
        float S1 = red[0][0] + red[1][0] + red[2][0] + red[3][0];
        float S2 = red[0][1] + red[1][1] + red[2][1] + red[3][1];
        float S3 = red[0][2] + red[1][2] + red[2][2] + red[3][2];
        bc2[0] = sqrtf(S1 + 1e-20f);
        bc2[1] = plin_f(tab[7], S2 * 0.1f + S3 * 0.01f);
    }
    __syncthreads();

    // ---- one_hot * conf, 11 outputs ----
    if (t < OBJ + 1) {
        float total = bc2[0], conf = bc2[1];
        float s = fminf(fmaxf(total, 0.0f), (float)OBJ);
        int i = (int)s;
        float f = s - truncf(s);
        int il = i < OBJ ? i : OBJ;
        int ir = (i + 1) < OBJ ? (i + 1) : OBJ;
        float v = (1.0f - f) * (t == il ? 1.0f : 0.0f) + f * (t == ir ? 1.0f : 0.0f);
        out[(size_t)row * (OBJ + 1) + t] = v * conf;
    }
}

extern "C" void kernel_launch(void* const* d_in, const int* in_sizes, int n_in,
                              void* d_out, int out_size) {
    const float* boxes     = (const float*)d_in[0];
    const float* attention = (const float*)d_in[1];
    const float* ws        = (const float*)d_in[2];
    float* out = (float*)d_out;
    int n = in_sizes[1] / MOBJ;
    counter_kernel<<<n, 128>>>(boxes, attention, ws, out, n);
}

// round 4
// speedup vs baseline: 2.0286x; 1.3256x over previous
#include <cuda_runtime.h>
#include <cuda_bf16.h>
#include <math.h>

#define N_PL 16
#define OBJ  10
#define MOBJ 36

// Precomputed once per launch by prep_kernel (row-invariant data):
__device__ float2 g_tab[136];     // 8 tables x 17: (A,B), plin(x) = A[i] + y*B[i], y=16x, i=(int)y
__device__ uchar4 g_pairs[128];   // per-thread (j55,k55,j45,k45)

__device__ __forceinline__ void pair55(int p, int& j, int& k) {
    int jj = (int)(10.5f - sqrtf(110.25f - 2.0f * (float)p));
    jj = max(0, min(9, jj));
    int base = (jj * (21 - jj)) >> 1;
    if (p < base) { jj--; base = (jj * (21 - jj)) >> 1; }
    else { int nb = ((jj + 1) * (20 - jj)) >> 1; if (p >= nb) { jj++; base = nb; } }
    j = jj; k = jj + (p - base);
}
__device__ __forceinline__ void pair45(int p, int& j, int& k) {
    int jj = (int)(9.5f - sqrtf(90.25f - 2.0f * (float)p));
    jj = max(0, min(8, jj));
    int base = (jj * (19 - jj)) >> 1;
    if (p < base) { jj--; base = (jj * (19 - jj)) >> 1; }
    else { int nb = ((jj + 1) * (18 - jj)) >> 1; if (p >= nb) { jj++; base = nb; } }
    j = jj; k = jj + 1 + (p - base);
}

__global__ void prep_kernel(const float* __restrict__ ws) {
    int t = threadIdx.x;
    if (t < 8) {
        float w[N_PL + 1];
        float s = 0.0f;
        for (int i = 0; i <= N_PL; i++) { w[i] = fabsf(ws[t * 17 + i]); s += w[i]; }
        float inv = 1.0f / s;
        float c = 0.0f;
        for (int i = 0; i <= N_PL; i++) {
            c += w[i] * inv;
            float wn = (i < N_PL) ? w[i + 1] * inv : 0.0f;
            g_tab[t * 17 + i] = make_float2(c - (float)i * wn, wn);
        }
    }
    int j5, k5; pair55(min(t, 54), j5, k5);
    int j4, k4; pair45(min(t >> 1, 44), j4, k4);
    g_pairs[t] = make_uchar4((unsigned char)j5, (unsigned char)k5,
                             (unsigned char)j4, (unsigned char)k4);
}

// plin with pre-scaled argument y = 16*x, y in [0,16] (tiny overshoot safe: trunc + continuity)
__device__ __forceinline__ float plin2(const float2* __restrict__ tb, float y) {
    int i = (int)y;
    float2 p = tb[i];
    return fmaf(y, p.y, p.x);
}

__global__ __launch_bounds__(128, 12)
void counter_kernel(const float* __restrict__ boxes,      // [n, 4, 36]
                    const float* __restrict__ attention,  // [n, 36]
                    float* __restrict__ out,              // [n, 11]
                    int n) {
    __shared__ float2 stab[136];
    __shared__ unsigned long long keys[MOBJ];
    __shared__ float att[OBJ];
    __shared__ float box4[4][OBJ];
    __shared__ float dedup[OBJ][OBJ];
    __shared__ float simM[OBJ][OBJ];
    __shared__ float score55[55];
    __shared__ float invr[OBJ];
    __shared__ float2 red[3];
    __shared__ float bc2[2];

    const int row = blockIdx.x;
    const int t = threadIdx.x;

    const uchar4 pr = g_pairs[t];
    const int j55 = pr.x, k55 = pr.y, j45 = pr.z, k45 = pr.w;
    const int h45 = t & 1;

    // table copy (all threads, 1-2 LDG.64 each)
    stab[t] = g_tab[t];
    if (t < 8) stab[128 + t] = g_tab[128 + t];

    // sortable 64-bit keys: (monotone uint of float << 32) | ~index  -> exact tie handling
    float myv = 0.0f;
    if (t < MOBJ) {
        myv = attention[(size_t)row * MOBJ + t];
        unsigned u = __float_as_uint(myv);
        unsigned s = (u & 0x80000000u) ? ~u : (u | 0x80000000u);
        keys[t] = ((unsigned long long)s << 32) | (unsigned)(~t);
    }
    __syncthreads();

    // ---- top-10 set via rank count, warp 0 only (dual accumulator for values 32..35) ----
    if (t < 32) {
        unsigned long long kv1 = keys[t];
        unsigned long long kv2 = keys[32 + (t & 3)];
        int r1 = 0, r2 = 0;
        #pragma unroll
        for (int j = 0; j < MOBJ; j++) {
            unsigned long long kj = keys[j];
            r1 += (kj > kv1);
            r2 += (kj > kv2);
        }
        if (r1 < OBJ) {
            att[r1] = __fdividef(1.0f, 1.0f + __expf(-myv));
            const float* bp = boxes + (size_t)row * (4 * MOBJ) + t;
            box4[0][r1] = bp[0];
            box4[1][r1] = bp[MOBJ];
            box4[2][r1] = bp[2 * MOBJ];
            box4[3][r1] = bp[3 * MOBJ];
        }
        if (t < 4 && r2 < OBJ) {
            float v2 = __ldg(&attention[(size_t)row * MOBJ + 32 + t]);
            att[r2] = __fdividef(1.0f, 1.0f + __expf(-v2));
            const float* bp = boxes + (size_t)row * (4 * MOBJ) + 32 + t;
            box4[0][r2] = bp[0];
            box4[1][r2] = bp[MOBJ];
            box4[2][r2] = bp[2 * MOBJ];
            box4[3][r2] = bp[3 * MOBJ];
        }
    }
    __syncthreads();

    const float2* tb0 = stab;
    const float2* tb1 = stab + 17;
    const float2* tb2 = stab + 34;
    const float2* tb3 = stab + 51;
    const float2* tb4 = stab + 68;

    // ---- pairwise (55 unordered pairs): dist, weighted score, dedup, weighted dconf ----
    float dCw = 0.0f;
    if (t < 55) {
        float ax0 = box4[0][j55], ay0 = box4[1][j55], ax1 = box4[2][j55], ay1 = box4[3][j55];
        float bx0 = box4[0][k55], by0 = box4[1][k55], bx1 = box4[2][k55], by1 = box4[3][k55];
        float iw = fmaxf(fminf(ax1, bx1) - fmaxf(ax0, bx0), 0.0f);
        float ih = fmaxf(fminf(ay1, by1) - fmaxf(ay0, by0), 0.0f);
        float inter = iw * ih;
        float aa = fmaxf(ax1 - ax0, 0.0f) * fmaxf(ay1 - ay0, 0.0f);
        float ab = fmaxf(bx1 - bx0, 0.0f) * fmaxf(by1 - by0, 0.0f);
        float d = 1.0f - __fdividef(inter, aa + ab - inter + 1e-12f);
        float yr = att[j55] * att[k55] * 16.0f;
        float yd = d * 16.0f;
        float wgt = (j55 == k55) ? 1.0f : 2.0f;
        score55[t] = wgt * plin2(tb0, yr) * plin2(tb1, yd);
        float dd = plin2(tb3, yr) * plin2(tb4, yd);
        dedup[j55][k55] = dd;
        dedup[k55][j55] = dd;
        dCw = wgt * fabsf(plin2(stab + 102, yd) - 0.5f);   // tb6
    }
    __syncthreads();

    // ---- sim: 45 strict pairs x 2 threads (warps 0-2 only; warp 3 writes diag) ----
    if (t < 96) {
        const int i0 = h45 * 5;
        float prod = 1.0f;
        #pragma unroll
        for (int i = 0; i < 5; i++) {
            float df = dedup[i0 + i][j45] - dedup[i0 + i][k45];
            prod *= plin2(tb2, fmaf(fabsf(df), -16.0f, 16.0f));
        }
        if (h45 == 0) {
            float da = att[j45] - att[k45];
            prod *= plin2(tb2, fmaf(fabsf(da), -16.0f, 16.0f));
        }
        prod *= __shfl_xor_sync(0xffffffffu, prod, 1);
        if (h45 == 0 && t < 90) { simM[j45][k45] = prod; simM[k45][j45] = prod; }
    } else if (t < 96 + OBJ) {
        simM[t - 96][t - 96] = 1.0f;    // diagonal: all diffs identically 0 -> csum[16]^11 ~= 1
    }
    __syncthreads();

    // ---- row_sims reciprocal ----
    if (t < OBJ) {
        float s = 0.0f;
        #pragma unroll
        for (int k = 0; k < OBJ; k++) s += simM[t][k];
        invr[t] = __fdividef(1.0f, s);
    }
    __syncthreads();

    // ---- partials: score/(rj*rk) [warps 0-1], correction + att_conf [warp 2] ----
    float sT = 0.0f, mC = 0.01f * dCw;
    if (t < 55) {
        sT = score55[t] * invr[j55] * invr[k55];
    }
    if (t >= 64 && t < 64 + OBJ) {
        const int q = t - 64;
        float a = att[q];
        sT = plin2(tb0, a * a * 16.0f) * invr[q];
        mC = 0.1f * fabsf(plin2(stab + 85, a * 16.0f) - 0.5f);   // tb5
    }

    // ---- reduction over warps 0-2 (2 accumulators) ----
    if (t < 96) {
        #pragma unroll
        for (int o = 16; o > 0; o >>= 1) {
            sT += __shfl_down_sync(0xffffffffu, sT, o);
            mC += __shfl_down_sync(0xffffffffu, mC, o);
        }
        if ((t & 31) == 0) red[t >> 5] = make_float2(sT, mC);
    }
    __syncthreads();

    if (t == 0) {
        float S = red[0].x + red[1].x + red[2].x;
        float M = red[0].y + red[1].y + red[2].y;
        bc2[0] = sqrtf(S + 1e-20f);
        bc2[1] = plin2(stab + 119, M * 16.0f);                   // tb7
    }
    __syncthreads();

    // ---- one_hot * conf, 11 outputs ----
    if (t < OBJ + 1) {
        float total = bc2[0], conf = bc2[1];
        float s = fminf(fmaxf(total, 0.0f), (float)OBJ);
        int i = (int)s;
        float f = s - truncf(s);
        int il = i < OBJ ? i : OBJ;
        int ir = (i + 1) < OBJ ? (i + 1) : OBJ;
        float v = (1.0f - f) * (t == il ? 1.0f : 0.0f) + f * (t == ir ? 1.0f : 0.0f);
        out[(size_t)row * (OBJ + 1) + t] = v * conf;
    }
}

extern "C" void kernel_launch(void* const* d_in, const int* in_sizes, int n_in,
                              void* d_out, int out_size) {
    const float* boxes     = (const float*)d_in[0];
    const float* attention = (const float*)d_in[1];
    const float* ws        = (const float*)d_in[2];
    float* out = (float*)d_out;
    int n = in_sizes[1] / MOBJ;
    prep_kernel<<<1, 128>>>(ws);
    counter_kernel<<<n, 128>>>(boxes, attention, out, n);
}

// round 5
// speedup vs baseline: 3.0870x; 1.5217x over previous
#include <cuda_runtime.h>
#include <cuda_bf16.h>
#include <math.h>

#define N_PL 16
#define OBJ  10
#define MOBJ 36
#define RPB  8     // rows (warps) per block

// Precomputed once per launch (row-invariant):
__device__ float2 g_tab[136];    // 8 tables x 17: plin(y) = A[i] + y*B[i], i=(int)y, y=16x
__device__ uchar4 g_pairA[32];   // per-lane: (j,k) for 55-pair l  and 55-pair 32+l
__device__ uchar4 g_pairB[32];   // per-lane: (j,k) for 45-pair l  and 45-pair 32+l

__device__ __forceinline__ void pair55(int p, int& j, int& k) {
    int jj = (int)(10.5f - sqrtf(110.25f - 2.0f * (float)p));
    jj = max(0, min(9, jj));
    int base = (jj * (21 - jj)) >> 1;
    if (p < base) { jj--; base = (jj * (21 - jj)) >> 1; }
    else { int nb = ((jj + 1) * (20 - jj)) >> 1; if (p >= nb) { jj++; base = nb; } }
    j = jj; k = jj + (p - base);
}
__device__ __forceinline__ void pair45(int p, int& j, int& k) {
    int jj = (int)(9.5f - sqrtf(90.25f - 2.0f * (float)p));
    jj = max(0, min(8, jj));
    int base = (jj * (19 - jj)) >> 1;
    if (p < base) { jj--; base = (jj * (19 - jj)) >> 1; }
    else { int nb = ((jj + 1) * (18 - jj)) >> 1; if (p >= nb) { jj++; base = nb; } }
    j = jj; k = jj + 1 + (p - base);
}

__global__ void prep_kernel(const float* __restrict__ ws) {
    int t = threadIdx.x;
    if (t < 8) {
        float w[N_PL + 1];
        float s = 0.0f;
        for (int i = 0; i <= N_PL; i++) { w[i] = fabsf(ws[t * 17 + i]); s += w[i]; }
        float inv = 1.0f / s;
        float c = 0.0f;
        for (int i = 0; i <= N_PL; i++) {
            c += w[i] * inv;
            float wn = (i < N_PL) ? w[i + 1] * inv : 0.0f;
            g_tab[t * 17 + i] = make_float2(c - (float)i * wn, wn);
        }
    }
    if (t >= 32 && t < 64) {
        int l = t - 32;
        int j1, k1; pair55(l, j1, k1);
        int p2 = (l < 23) ? 32 + l : 54;
        int j2, k2; pair55(p2, j2, k2);
        g_pairA[l] = make_uchar4((unsigned char)j1, (unsigned char)k1,
                                 (unsigned char)j2, (unsigned char)k2);
        int ja, ka; pair45(l < 45 ? l : 44, ja, ka);
        int q2 = (l < 13) ? 32 + l : 44;
        int jb, kb; pair45(q2, jb, kb);
        g_pairB[l] = make_uchar4((unsigned char)ja, (unsigned char)ka,
                                 (unsigned char)jb, (unsigned char)kb);
    }
}

// plin on pre-scaled argument y = 16*x (y in [0,16]; trunc + continuity make edges exact)
__device__ __forceinline__ float plin2(const float2* __restrict__ tb, float y) {
    int i = (int)y;
    float2 p = tb[i];
    return fmaf(y, p.y, p.x);
}

__global__ __launch_bounds__(256, 5)
void counter_kernel(const float* __restrict__ boxes,      // [n, 4, 36]
                    const float* __restrict__ attention,  // [n, 36]
                    float* __restrict__ out,              // [n, 11]
                    int n) {
    __shared__ float2 stab[136];
    __shared__ float  akey[RPB][MOBJ];
    __shared__ float  att[RPB][OBJ];
    __shared__ float4 boxs[RPB][OBJ];
    __shared__ float  dedup[RPB][OBJ * OBJ];
    __shared__ float  simM[RPB][OBJ * OBJ];
    __shared__ float  invr[RPB][OBJ];

    const int t = threadIdx.x;
    const int w = t >> 5, l = t & 31;
    const int row = blockIdx.x * RPB + w;
    const bool act = row < n;

    if (t < 136) stab[t] = g_tab[t];

    // ---- attention loads (36 = 32 lanes + lanes 0..3 take extras) ----
    float v1 = 0.0f, v2 = 0.0f;
    if (act) {
        v1 = attention[(size_t)row * MOBJ + l];
        if (l < 4) v2 = attention[(size_t)row * MOBJ + 32 + l];
    }
    akey[w][l] = v1;
    if (l < 4) akey[w][32 + l] = v2;
    __syncthreads();   // the ONLY block-wide barrier (covers stab + akey)

    // ---- top-10 set via rank count (order-invariant; ties by lower index) ----
    int r1 = 0, r2 = 0;
    const float* ak = akey[w];
    #pragma unroll
    for (int j = 0; j < MOBJ; j++) {
        float aj = ak[j];                    // uniform-address broadcast LDS
        r1 += (aj > v1) || (aj == v1 && j < l);
        r2 += (aj > v2) || (aj == v2 && j < 32 + l);
    }
    if (act && r1 < OBJ) {
        att[w][r1] = __fdividef(1.0f, 1.0f + __expf(-v1));
        const float* bp = boxes + (size_t)row * (4 * MOBJ) + l;
        boxs[w][r1] = make_float4(bp[0], bp[MOBJ], bp[2 * MOBJ], bp[3 * MOBJ]);
    }
    if (act && l < 4 && r2 < OBJ) {
        att[w][r2] = __fdividef(1.0f, 1.0f + __expf(-v2));
        const float* bp = boxes + (size_t)row * (4 * MOBJ) + 32 + l;
        boxs[w][r2] = make_float4(bp[0], bp[MOBJ], bp[2 * MOBJ], bp[3 * MOBJ]);
    }
    __syncwarp();

    // ---- pairwise (55 unordered pairs: lane l does pair l, lanes 0-22 also 32+l) ----
    const uchar4 pa = g_pairA[l];
    const float* aw = att[w];
    float* ddw = dedup[w];
    float dC, sc1, sc2 = 0.0f;
    {
        const int j = pa.x, k = pa.y;
        float4 A = boxs[w][j], B = boxs[w][k];
        float iw = fmaxf(fminf(A.z, B.z) - fmaxf(A.x, B.x), 0.0f);
        float ih = fmaxf(fminf(A.w, B.w) - fmaxf(A.y, B.y), 0.0f);
        float inter = iw * ih;
        float aa = fmaxf(A.z - A.x, 0.0f) * fmaxf(A.w - A.y, 0.0f);
        float ab = fmaxf(B.z - B.x, 0.0f) * fmaxf(B.w - B.y, 0.0f);
        float d = 1.0f - __fdividef(inter, aa + ab - inter + 1e-12f);
        float yr = aw[j] * aw[k] * 16.0f;
        float yd = d * 16.0f;
        float wgt = (j == k) ? 1.0f : 2.0f;
        sc1 = wgt * plin2(stab, yr) * plin2(stab + 17, yd);
        float dd = plin2(stab + 51, yr) * plin2(stab + 68, yd);
        ddw[j * OBJ + k] = dd;
        ddw[k * OBJ + j] = dd;
        dC = wgt * fabsf(plin2(stab + 102, yd) - 0.5f);
    }
    if (l < 23) {
        const int j = pa.z, k = pa.w;
        float4 A = boxs[w][j], B = boxs[w][k];
        float iw = fmaxf(fminf(A.z, B.z) - fmaxf(A.x, B.x), 0.0f);
        float ih = fmaxf(fminf(A.w, B.w) - fmaxf(A.y, B.y), 0.0f);
        float inter = iw * ih;
        float aa = fmaxf(A.z - A.x, 0.0f) * fmaxf(A.w - A.y, 0.0f);
        float ab = fmaxf(B.z - B.x, 0.0f) * fmaxf(B.w - B.y, 0.0f);
        float d = 1.0f - __fdividef(inter, aa + ab - inter + 1e-12f);
        float yr = aw[j] * aw[k] * 16.0f;
        float yd = d * 16.0f;
        float wgt = (j == k) ? 1.0f : 2.0f;
        sc2 = wgt * plin2(stab, yr) * plin2(stab + 17, yd);
        float dd = plin2(stab + 51, yr) * plin2(stab + 68, yd);
        ddw[j * OBJ + k] = dd;
        ddw[k * OBJ + j] = dd;
        dC += wgt * fabsf(plin2(stab + 102, yd) - 0.5f);
    }
    __syncwarp();

    // ---- sim (45 strict pairs: lane l does pair l, lanes 0-12 also 32+l; 22-31 diag) ----
    const uchar4 pb = g_pairB[l];
    const float2* tb2 = stab + 34;
    float* smw = simM[w];
    {
        const int j = pb.x, k = pb.y;
        float prod = 1.0f;
        #pragma unroll
        for (int i = 0; i < OBJ; i++) {
            float df = ddw[i * OBJ + j] - ddw[i * OBJ + k];
            prod *= plin2(tb2, fmaf(fabsf(df), -16.0f, 16.0f));
        }
        prod *= plin2(tb2, fmaf(fabsf(aw[j] - aw[k]), -16.0f, 16.0f));
        smw[j * OBJ + k] = prod;
        smw[k * OBJ + j] = prod;
    }
    if (l < 13) {
        const int j = pb.z, k = pb.w;
        float prod = 1.0f;
        #pragma unroll
        for (int i = 0; i < OBJ; i++) {
            float df = ddw[i * OBJ + j] - ddw[i * OBJ + k];
            prod *= plin2(tb2, fmaf(fabsf(df), -16.0f, 16.0f));
        }
        prod *= plin2(tb2, fmaf(fabsf(aw[j] - aw[k]), -16.0f, 16.0f));
        smw[j * OBJ + k] = prod;
        smw[k * OBJ + j] = prod;
    } else if (l >= 22) {
        smw[(l - 22) * (OBJ + 1)] = 1.0f;   // diagonal: diffs identically 0 -> product == 1
    }
    __syncwarp();

    // ---- row_sims reciprocal (lanes 0-9) ----
    if (l < OBJ) {
        float s = 0.0f;
        #pragma unroll
        for (int k = 0; k < OBJ; k++) s += smw[l * OBJ + k];
        invr[w][l] = __fdividef(1.0f, s);
    }
    __syncwarp();

    // ---- partials: scores (registers) / (rj*rk), correction + confs ----
    const float* ivw = invr[w];
    float sT = sc1 * ivw[pa.x] * ivw[pa.y];
    if (l < 23) sT += sc2 * ivw[pa.z] * ivw[pa.w];
    float mC = 0.01f * dC;
    if (l < OBJ) {
        float a = aw[l];
        sT += plin2(stab, a * a * 16.0f) * ivw[l];
        mC += 0.1f * fabsf(plin2(stab + 85, a * 16.0f) - 0.5f);
    }

    // ---- butterfly reduction: every lane ends with full sums ----
    #pragma unroll
    for (int o = 16; o > 0; o >>= 1) {
        sT += __shfl_xor_sync(0xffffffffu, sT, o);
        mC += __shfl_xor_sync(0xffffffffu, mC, o);
    }
    float total = sqrtf(sT + 1e-20f);
    float conf  = plin2(stab + 119, mC * 16.0f);

    // ---- one_hot * conf, lanes 0-10 write ----
    if (act && l < OBJ + 1) {
        float s = fminf(fmaxf(total, 0.0f), (float)OBJ);
        int i = (int)s;
        float f = s - truncf(s);
        int il = i < OBJ ? i : OBJ;
        int ir = (i + 1) < OBJ ? (i + 1) : OBJ;
        float v = (1.0f - f) * (l == il ? 1.0f : 0.0f) + f * (l == ir ? 1.0f : 0.0f);
        out[(size_t)row * (OBJ + 1) + l] = v * conf;
    }
}

extern "C" void kernel_launch(void* const* d_in, const int* in_sizes, int n_in,
                              void* d_out, int out_size) {
    const float* boxes     = (const float*)d_in[0];
    const float* attention = (const float*)d_in[1];
    const float* ws        = (const float*)d_in[2];
    float* out = (float*)d_out;
    int n = in_sizes[1] / MOBJ;
    prep_kernel<<<1, 64>>>(ws);
    counter_kernel<<<(n + RPB - 1) / RPB, 256>>>(boxes, attention, out, n);
}

// round 6
// speedup vs baseline: 3.1732x; 1.0279x over previous
#include <cuda_runtime.h>
#include <cuda_bf16.h>
#include <math.h>

#define N_PL 16
#define OBJ  10
#define MOBJ 36
#define RPB  8     // rows (warps) per block
#define STR  12    // padded row stride for 10x10 matrices (48B, 16B-aligned)

typedef unsigned long long ull;

// Precomputed once per launch (row-invariant):
__device__ float2 g_tab[136];    // 8 tables x 17: plin(y) = A[i] + y*B[i], i=(int)y, y=16x
__device__ uchar4 g_pairA[32];   // per-lane: (j,k) for 55-pair l and 55-pair 32+l
__device__ uchar4 g_pairB[32];   // per-lane: (j,k) for 45-pair l and 45-pair 32+l

__device__ __forceinline__ void pair55(int p, int& j, int& k) {
    int jj = (int)(10.5f - sqrtf(110.25f - 2.0f * (float)p));
    jj = max(0, min(9, jj));
    int base = (jj * (21 - jj)) >> 1;
    if (p < base) { jj--; base = (jj * (21 - jj)) >> 1; }
    else { int nb = ((jj + 1) * (20 - jj)) >> 1; if (p >= nb) { jj++; base = nb; } }
    j = jj; k = jj + (p - base);
}
__device__ __forceinline__ void pair45(int p, int& j, int& k) {
    int jj = (int)(9.5f - sqrtf(90.25f - 2.0f * (float)p));
    jj = max(0, min(8, jj));
    int base = (jj * (19 - jj)) >> 1;
    if (p < base) { jj--; base = (jj * (19 - jj)) >> 1; }
    else { int nb = ((jj + 1) * (18 - jj)) >> 1; if (p >= nb) { jj++; base = nb; } }
    j = jj; k = jj + 1 + (p - base);
}

__global__ void prep_kernel(const float* __restrict__ ws) {
    int t = threadIdx.x;
    if (t < 8) {
        float w[N_PL + 1];
        float s = 0.0f;
        for (int i = 0; i <= N_PL; i++) { w[i] = fabsf(ws[t * 17 + i]); s += w[i]; }
        float inv = 1.0f / s;
        float c = 0.0f;
        for (int i = 0; i <= N_PL; i++) {
            c += w[i] * inv;
            float wn = (i < N_PL) ? w[i + 1] * inv : 0.0f;
            g_tab[t * 17 + i] = make_float2(c - (float)i * wn, wn);
        }
    }
    if (t >= 32 && t < 64) {
        int l = t - 32;
        int j1, k1; pair55(l, j1, k1);
        int j2, k2; pair55((l < 23) ? 32 + l : 54, j2, k2);
        g_pairA[l] = make_uchar4((unsigned char)j1, (unsigned char)k1,
                                 (unsigned char)j2, (unsigned char)k2);
        int ja, ka; pair45(l < 45 ? l : 44, ja, ka);
        int jb, kb; pair45((l < 13) ? 32 + l : 44, jb, kb);
        g_pairB[l] = make_uchar4((unsigned char)ja, (unsigned char)ka,
                                 (unsigned char)jb, (unsigned char)kb);
    }
}

// plin on pre-scaled argument y = 16*x. Matches the jnp reference at/past both
// edges: y<0 -> i=0 (trunc), linear extension; y in [16,17) -> A[16] (B[16]=0).
__device__ __forceinline__ float plin2(const float2* __restrict__ tb, float y) {
    int i = (int)y;
    float2 p = tb[i];
    return fmaf(y, p.y, p.x);
}

// product of 10 plin(1-|colj[i]-colk[i]|) terms + the att term, vectorized column reads
__device__ __forceinline__ float simprod(const float* __restrict__ ddT,
                                         const float2* __restrict__ tb2,
                                         int j, int k, float aj, float ak) {
    const float4* cj = (const float4*)(ddT + j * STR);
    const float4* ck = (const float4*)(ddT + k * STR);
    float4 a0 = cj[0], b0 = ck[0];
    float p =  plin2(tb2, fmaf(fabsf(a0.x - b0.x), -16.0f, 16.0f));
    p *= plin2(tb2, fmaf(fabsf(a0.y - b0.y), -16.0f, 16.0f));
    p *= plin2(tb2, fmaf(fabsf(a0.z - b0.z), -16.0f, 16.0f));
    p *= plin2(tb2, fmaf(fabsf(a0.w - b0.w), -16.0f, 16.0f));
    float4 a1 = cj[1], b1 = ck[1];
    p *= plin2(tb2, fmaf(fabsf(a1.x - b1.x), -16.0f, 16.0f));
    p *= plin2(tb2, fmaf(fabsf(a1.y - b1.y), -16.0f, 16.0f));
    p *= plin2(tb2, fmaf(fabsf(a1.z - b1.z), -16.0f, 16.0f));
    p *= plin2(tb2, fmaf(fabsf(a1.w - b1.w), -16.0f, 16.0f));
    float2 a2 = *(const float2*)(ddT + j * STR + 8);
    float2 b2 = *(const float2*)(ddT + k * STR + 8);
    p *= plin2(tb2, fmaf(fabsf(a2.x - b2.x), -16.0f, 16.0f));
    p *= plin2(tb2, fmaf(fabsf(a2.y - b2.y), -16.0f, 16.0f));
    p *= plin2(tb2, fmaf(fabsf(aj - ak), -16.0f, 16.0f));
    return p;
}

__global__ __launch_bounds__(256, 5)
void counter_kernel(const float* __restrict__ boxes,      // [n, 4, 36]
                    const float* __restrict__ attention,  // [n, 36]
                    float* __restrict__ out,              // [n, 11]
                    int n) {
    __shared__ float2     stab[136];
    __shared__ ulonglong2 karr[RPB][16];   // 32 lane keys
    __shared__ ulonglong2 kext[RPB][2];    // 4 extra keys (elements 32..35)
    __shared__ float      att[RPB][OBJ];
    __shared__ float4     boxs[RPB][OBJ];
    __shared__ float      ddT[RPB][OBJ * STR];
    __shared__ float      smP[RPB][OBJ * STR];
    __shared__ float      invr[RPB][OBJ];

    const int t = threadIdx.x;
    const int w = t >> 5, l = t & 31;
    const int row = blockIdx.x * RPB + w;
    const bool act = row < n;

    if (t < 136) stab[t] = g_tab[t];

    // ---- load attention, build unique 64-bit sortable keys ----
    float v1 = 0.0f, v2 = 0.0f;
    if (act) {
        v1 = attention[(size_t)row * MOBJ + l];
        if (l < 4) v2 = attention[(size_t)row * MOBJ + 32 + l];
    }
    unsigned u1 = __float_as_uint(v1);
    unsigned s1 = (u1 & 0x80000000u) ? ~u1 : (u1 | 0x80000000u);
    ull kv1 = ((ull)s1 << 32) | (unsigned)~(unsigned)l;
    ((ull*)karr[w])[l] = kv1;
    unsigned u2 = __float_as_uint(v2);
    unsigned s2 = (u2 & 0x80000000u) ? ~u2 : (u2 | 0x80000000u);
    ull kv2 = ((ull)s2 << 32) | (unsigned)~(unsigned)(32 + l);
    if (l < 4) ((ull*)kext[w])[l] = kv2;
    __syncthreads();   // covers stab + this warp's keys

    // ---- rank of lane element among all 36 (strict key >) ----
    int r1 = 0;
    {
        const ulonglong2* kp = karr[w];
        #pragma unroll
        for (int p = 0; p < 16; p++) {
            ulonglong2 kk = kp[p];
            r1 += (kk.x > kv1);
            r1 += (kk.y > kv1);
        }
    }
    ulonglong2 e01 = kext[w][0], e23 = kext[w][1];
    r1 += (e01.x > kv1) + (e01.y > kv1) + (e23.x > kv1) + (e23.y > kv1);

    // ---- ranks of the 4 extras via ballots ----
    unsigned b0 = __ballot_sync(0xffffffffu, kv1 > e01.x);
    unsigned b1 = __ballot_sync(0xffffffffu, kv1 > e01.y);
    unsigned b2 = __ballot_sync(0xffffffffu, kv1 > e23.x);
    unsigned b3 = __ballot_sync(0xffffffffu, kv1 > e23.y);
    int r2 = (l == 0) ? __popc(b0) : (l == 1) ? __popc(b1) : (l == 2) ? __popc(b2) : __popc(b3);
    r2 += (e01.x > kv2) + (e01.y > kv2) + (e23.x > kv2) + (e23.y > kv2);

    // ---- gather selected objects ----
    if (act && r1 < OBJ) {
        att[w][r1] = __fdividef(1.0f, 1.0f + __expf(-v1));
        const float* bp = boxes + (size_t)row * (4 * MOBJ) + l;
        boxs[w][r1] = make_float4(bp[0], bp[MOBJ], bp[2 * MOBJ], bp[3 * MOBJ]);
    }
    if (act && l < 4 && r2 < OBJ) {
        att[w][r2] = __fdividef(1.0f, 1.0f + __expf(-v2));
        const float* bp = boxes + (size_t)row * (4 * MOBJ) + 32 + l;
        boxs[w][r2] = make_float4(bp[0], bp[MOBJ], bp[2 * MOBJ], bp[3 * MOBJ]);
    }
    __syncwarp();

    // ---- pairwise (55 pairs: lane l does pair l; lanes 0-22 also pair 32+l) ----
    const uchar4 pa = g_pairA[l];
    const float* aw = att[w];
    float* dT = ddT[w];
    float dC, sc1, sc2 = 0.0f;
    {
        const int j = pa.x, k = pa.y;
        float4 A = boxs[w][j], B = boxs[w][k];
        float iw = fmaxf(fminf(A.z, B.z) - fmaxf(A.x, B.x), 0.0f);
        float ih = fmaxf(fminf(A.w, B.w) - fmaxf(A.y, B.y), 0.0f);
        float inter = iw * ih;
        float aa = fmaxf(A.z - A.x, 0.0f) * fmaxf(A.w - A.y, 0.0f);
        float ab = fmaxf(B.z - B.x, 0.0f) * fmaxf(B.w - B.y, 0.0f);
        float d = 1.0f - __fdividef(inter, aa + ab - inter + 1e-12f);
        float yr = aw[j] * aw[k] * 16.0f;
        float yd = d * 16.0f;
        float wgt = (j == k) ? 1.0f : 2.0f;
        sc1 = wgt * plin2(stab, yr) * plin2(stab + 17, yd);
        float dd = plin2(stab + 51, yr) * plin2(stab + 68, yd);
        dT[j * STR + k] = dd;
        dT[k * STR + j] = dd;
        dC = wgt * fabsf(plin2(stab + 102, yd) - 0.5f);
    }
    if (l < 23) {
        const int j = pa.z, k = pa.w;
        float4 A = boxs[w][j], B = boxs[w][k];
        float iw = fmaxf(fminf(A.z, B.z) - fmaxf(A.x, B.x), 0.0f);
        float ih = fmaxf(fminf(A.w, B.w) - fmaxf(A.y, B.y), 0.0f);
        float inter = iw * ih;
        float aa = fmaxf(A.z - A.x, 0.0f) * fmaxf(A.w - A.y, 0.0f);
        float ab = fmaxf(B.z - B.x, 0.0f) * fmaxf(B.w - B.y, 0.0f);
        float d = 1.0f - __fdividef(inter, aa + ab - inter + 1e-12f);
        float yr = aw[j] * aw[k] * 16.0f;
        float yd = d * 16.0f;
        float wgt = (j == k) ? 1.0f : 2.0f;
        sc2 = wgt * plin2(stab, yr) * plin2(stab + 17, yd);
        float dd = plin2(stab + 51, yr) * plin2(stab + 68, yd);
        dT[j * STR + k] = dd;
        dT[k * STR + j] = dd;
        dC += wgt * fabsf(plin2(stab + 102, yd) - 0.5f);
    }
    __syncwarp();

    // ---- sim (45 strict pairs: lane l does pair l; lanes 0-12 also 32+l; 22-31 diag) ----
    const uchar4 pb = g_pairB[l];
    const float2* tb2 = stab + 34;
    float* sP = smP[w];
    {
        float prod = simprod(dT, tb2, pb.x, pb.y, aw[pb.x], aw[pb.y]);
        sP[pb.x * STR + pb.y] = prod;
        sP[pb.y * STR + pb.x] = prod;
    }
    if (l < 13) {
        float prod = simprod(dT, tb2, pb.z, pb.w, aw[pb.z], aw[pb.w]);
        sP[pb.z * STR + pb.w] = prod;
        sP[pb.w * STR + pb.z] = prod;
    } else if (l >= 22) {
        sP[(l - 22) * (STR + 1)] = 1.0f;   // diagonal: diffs identically 0 -> product == 1
    }
    __syncwarp();

    // ---- row_sims reciprocal (lanes 0-9, vectorized) ----
    if (l < OBJ) {
        const float4* rp = (const float4*)(sP + l * STR);
        float4 x0 = rp[0], x1 = rp[1];
        float2 x2 = *(const float2*)(sP + l * STR + 8);
        float s = ((x0.x + x0.y) + (x0.z + x0.w)) + ((x1.x + x1.y) + (x1.z + x1.w)) + (x2.x + x2.y);
        invr[w][l] = __fdividef(1.0f, s);
    }
    __syncwarp();

    // ---- partials: scores (held in regs) / (rj*rk); correction + confs ----
    const float* ivw = invr[w];
    float sT = sc1 * ivw[pa.x] * ivw[pa.y];
    if (l < 23) sT += sc2 * ivw[pa.z] * ivw[pa.w];
    float mC = 0.01f * dC;
    if (l < OBJ) {
        float a = aw[l];
        sT += plin2(stab, a * a * 16.0f) * ivw[l];
        mC += 0.1f * fabsf(plin2(stab + 85, a * 16.0f) - 0.5f);
    }

    // ---- butterfly reduction ----
    #pragma unroll
    for (int o = 16; o > 0; o >>= 1) {
        sT += __shfl_xor_sync(0xffffffffu, sT, o);
        mC += __shfl_xor_sync(0xffffffffu, mC, o);
    }
    float total = sqrtf(sT + 1e-20f);
    float conf  = plin2(stab + 119, mC * 16.0f);

    // ---- one_hot * conf, lanes 0-10 ----
    if (act && l < OBJ + 1) {
        float s = fminf(fmaxf(total, 0.0f), (float)OBJ);
        int i = (int)s;
        float f = s - truncf(s);
        int il = i < OBJ ? i : OBJ;
        int ir = (i + 1) < OBJ ? (i + 1) : OBJ;
        float v = (1.0f - f) * (l == il ? 1.0f : 0.0f) + f * (l == ir ? 1.0f : 0.0f);
        out[(size_t)row * (OBJ + 1) + l] = v * conf;
    }
}

extern "C" void kernel_launch(void* const* d_in, const int* in_sizes, int n_in,
                              void* d_out, int out_size) {
    const float* boxes     = (const float*)d_in[0];
    const float* attention = (const float*)d_in[1];
    const float* ws        = (const float*)d_in[2];
    float* out = (float*)d_out;
    int n = in_sizes[1] / MOBJ;
    prep_kernel<<<1, 64>>>(ws);
    counter_kernel<<<(n + RPB - 1) / RPB, 256>>>(boxes, attention, out, n);
}

// round 7
// speedup vs baseline: 3.2769x; 1.0327x over previous
#include <cuda_runtime.h>
#include <cuda_bf16.h>
#include <math.h>

#define N_PL 16
#define OBJ  10
#define MOBJ 36
#define RPB  8     // rows (warps) per block
#define STR  12    // padded row stride for 10x10 matrices (48B, 16B-aligned)

typedef unsigned long long ull;

// Compile-time pair tables (static .global data; coalesced 128B LDG per warp).
// pairA[l] = (j,k) of 55-pair l  and (j,k) of 55-pair 32+l (lanes 0-22; dc after)
__device__ const uchar4 g_pairA[32] = {
    {0,0,3,8},{0,1,3,9},{0,2,4,4},{0,3,4,5},{0,4,4,6},{0,5,4,7},{0,6,4,8},{0,7,4,9},
    {0,8,5,5},{0,9,5,6},{1,1,5,7},{1,2,5,8},{1,3,5,9},{1,4,6,6},{1,5,6,7},{1,6,6,8},
    {1,7,6,9},{1,8,7,7},{1,9,7,8},{2,2,7,9},{2,3,8,8},{2,4,8,9},{2,5,9,9},{2,6,9,9},
    {2,7,9,9},{2,8,9,9},{2,9,9,9},{3,3,9,9},{3,4,9,9},{3,5,9,9},{3,6,9,9},{3,7,9,9}};
// pairB[l] = (j,k) of 45-pair l  and (j,k) of 45-pair 32+l (lanes 0-12; dc after)
__device__ const uchar4 g_pairB[32] = {
    {0,1,4,7},{0,2,4,8},{0,3,4,9},{0,4,5,6},{0,5,5,7},{0,6,5,8},{0,7,5,9},{0,8,6,7},
    {0,9,6,8},{1,2,6,9},{1,3,7,8},{1,4,7,9},{1,5,8,9},{1,6,8,9},{1,7,8,9},{1,8,8,9},
    {1,9,8,9},{2,3,8,9},{2,4,8,9},{2,5,8,9},{2,6,8,9},{2,7,8,9},{2,8,8,9},{2,9,8,9},
    {3,4,8,9},{3,5,8,9},{3,6,8,9},{3,7,8,9},{3,8,8,9},{3,9,8,9},{4,5,8,9},{4,6,8,9}};

// plin on pre-scaled argument y = 16*x, y in [0,16]; table row: plin = A[i] + y*B[i]
__device__ __forceinline__ float plin2(const float2* __restrict__ tb, float y) {
    int i = (int)y;
    float2 p = tb[i];
    return fmaf(y, p.y, p.x);
}

// product of 10 plin(1-|colj[i]-colk[i]|) terms + att4 term, vectorized column reads
__device__ __forceinline__ float simprod(const float* __restrict__ ddT,
                                         const float2* __restrict__ tb2,
                                         int j, int k, float a4j, float a4k) {
    const float4* cj = (const float4*)(ddT + j * STR);
    const float4* ck = (const float4*)(ddT + k * STR);
    float4 a0 = cj[0], b0 = ck[0];
    float p =  plin2(tb2, fmaf(fabsf(a0.x - b0.x), -16.0f, 16.0f));
    p *= plin2(tb2, fmaf(fabsf(a0.y - b0.y), -16.0f, 16.0f));
    p *= plin2(tb2, fmaf(fabsf(a0.z - b0.z), -16.0f, 16.0f));
    p *= plin2(tb2, fmaf(fabsf(a0.w - b0.w), -16.0f, 16.0f));
    float4 a1 = cj[1], b1 = ck[1];
    p *= plin2(tb2, fmaf(fabsf(a1.x - b1.x), -16.0f, 16.0f));
    p *= plin2(tb2, fmaf(fabsf(a1.y - b1.y), -16.0f, 16.0f));
    p *= plin2(tb2, fmaf(fabsf(a1.z - b1.z), -16.0f, 16.0f));
    p *= plin2(tb2, fmaf(fabsf(a1.w - b1.w), -16.0f, 16.0f));
    float2 a2 = *(const float2*)(ddT + j * STR + 8);
    float2 b2 = *(const float2*)(ddT + k * STR + 8);
    p *= plin2(tb2, fmaf(fabsf(a2.x - b2.x), -16.0f, 16.0f));
    p *= plin2(tb2, fmaf(fabsf(a2.y - b2.y), -16.0f, 16.0f));
    p *= plin2(tb2, fmaf(fabsf(a4j - a4k), -4.0f, 16.0f));   // att stored x4
    return p;
}

__global__ __launch_bounds__(256, 5)
void counter_kernel(const float* __restrict__ boxes,      // [n, 4, 36]
                    const float* __restrict__ attention,  // [n, 36]
                    const float* __restrict__ ws,         // [8, 17]
                    float* __restrict__ out,              // [n, 11]
                    int n) {
    __shared__ float2     stab[8 * 17];
    __shared__ ulonglong2 karr[RPB][16];
    __shared__ ulonglong2 kext[RPB][2];
    __shared__ float      att[RPB][OBJ];     // holds 4*sigmoid
    __shared__ float4     boxs[RPB][OBJ];
    __shared__ float      ddT[RPB][OBJ * STR];
    __shared__ float      smP[RPB][OBJ * STR];
    __shared__ float      invr[RPB][OBJ];

    const int t = threadIdx.x;
    const int w = t >> 5, l = t & 31;
    const int row = blockIdx.x * RPB + w;
    const bool act = row < n;

    // ---- plin table w built by warp w: |ws|, shfl inclusive scan, normalize ----
    {
        float wv0 = (l <= N_PL) ? fabsf(ws[w * 17 + l]) : 0.0f;
        float cs = wv0;
        #pragma unroll
        for (int o = 1; o <= 16; o <<= 1) {
            float up = __shfl_up_sync(0xffffffffu, cs, o);
            if (l >= o) cs += up;
        }
        float total = __shfl_sync(0xffffffffu, cs, N_PL);
        float inv = __fdividef(1.0f, total);
        float wnext = __shfl_down_sync(0xffffffffu, wv0, 1);
        float B = (l < N_PL) ? wnext * inv : 0.0f;
        float A = fmaf(-(float)l, B, cs * inv);
        if (l <= N_PL) stab[w * 17 + l] = make_float2(A, B);
    }

    // ---- load attention, build unique 64-bit sortable keys ----
    float v1 = 0.0f, v2 = 0.0f;
    if (act) {
        v1 = attention[(size_t)row * MOBJ + l];
        if (l < 4) v2 = attention[(size_t)row * MOBJ + 32 + l];
    }
    unsigned u1 = __float_as_uint(v1);
    unsigned s1 = (u1 & 0x80000000u) ? ~u1 : (u1 | 0x80000000u);
    ull kv1 = ((ull)s1 << 32) | (unsigned)~(unsigned)l;
    ((ull*)karr[w])[l] = kv1;
    unsigned u2 = __float_as_uint(v2);
    unsigned s2 = (u2 & 0x80000000u) ? ~u2 : (u2 | 0x80000000u);
    ull kv2 = ((ull)s2 << 32) | (unsigned)~(unsigned)(32 + l);
    if (l < 4) ((ull*)kext[w])[l] = kv2;
    __syncthreads();   // the ONLY block barrier: stab (cross-warp) + own keys

    // ---- rank among all 36 (strict key >) ----
    int r1 = 0;
    {
        const ulonglong2* kp = karr[w];
        #pragma unroll
        for (int p = 0; p < 16; p++) {
            ulonglong2 kk = kp[p];
            r1 += (kk.x > kv1);
            r1 += (kk.y > kv1);
        }
    }
    ulonglong2 e01 = kext[w][0], e23 = kext[w][1];
    r1 += (e01.x > kv1) + (e01.y > kv1) + (e23.x > kv1) + (e23.y > kv1);

    // ---- ranks of the 4 extras via ballots ----
    unsigned b0 = __ballot_sync(0xffffffffu, kv1 > e01.x);
    unsigned b1 = __ballot_sync(0xffffffffu, kv1 > e01.y);
    unsigned b2 = __ballot_sync(0xffffffffu, kv1 > e23.x);
    unsigned b3 = __ballot_sync(0xffffffffu, kv1 > e23.y);
    int r2 = (l == 0) ? __popc(b0) : (l == 1) ? __popc(b1) : (l == 2) ? __popc(b2) : __popc(b3);
    r2 += (e01.x > kv2) + (e01.y > kv2) + (e23.x > kv2) + (e23.y > kv2);

    // ---- gather selected objects (att stored as 4*sigmoid) ----
    if (act && r1 < OBJ) {
        att[w][r1] = __fdividef(4.0f, 1.0f + __expf(-v1));
        const float* bp = boxes + (size_t)row * (4 * MOBJ) + l;
        boxs[w][r1] = make_float4(bp[0], bp[MOBJ], bp[2 * MOBJ], bp[3 * MOBJ]);
    }
    if (act && l < 4 && r2 < OBJ) {
        att[w][r2] = __fdividef(4.0f, 1.0f + __expf(-v2));
        const float* bp = boxes + (size_t)row * (4 * MOBJ) + 32 + l;
        boxs[w][r2] = make_float4(bp[0], bp[MOBJ], bp[2 * MOBJ], bp[3 * MOBJ]);
    }
    __syncwarp();

    // ---- pairwise (55 pairs: lane l; lanes 0-22 also pair 32+l) ----
    const uchar4 pa = g_pairA[l];
    const float* aw = att[w];
    float* dT = ddT[w];
    float dC, sc1, sc2 = 0.0f;
    {
        const int j = pa.x, k = pa.y;
        float4 A = boxs[w][j], B = boxs[w][k];
        float iw = fmaxf(fminf(A.z, B.z) - fmaxf(A.x, B.x), 0.0f);
        float ih = fmaxf(fminf(A.w, B.w) - fmaxf(A.y, B.y), 0.0f);
        float inter = iw * ih;
        float aa = fmaxf(A.z - A.x, 0.0f) * fmaxf(A.w - A.y, 0.0f);
        float ab = fmaxf(B.z - B.x, 0.0f) * fmaxf(B.w - B.y, 0.0f);
        float d = 1.0f - __fdividef(inter, aa + ab - inter + 1e-12f);
        float yr = aw[j] * aw[k];          // (4a)(4a) = 16*rel
        float yd = d * 16.0f;
        float wgt = (j == k) ? 1.0f : 2.0f;
        sc1 = wgt * plin2(stab, yr) * plin2(stab + 17, yd);
        float dd = plin2(stab + 51, yr) * plin2(stab + 68, yd);
        dT[j * STR + k] = dd;
        dT[k * STR + j] = dd;
        dC = wgt * fabsf(plin2(stab + 102, yd) - 0.5f);
    }
    if (l < 23) {
        const int j = pa.z, k = pa.w;
        float4 A = boxs[w][j], B = boxs[w][k];
        float iw = fmaxf(fminf(A.z, B.z) - fmaxf(A.x, B.x), 0.0f);
        float ih = fmaxf(fminf(A.w, B.w) - fmaxf(A.y, B.y), 0.0f);
        float inter = iw * ih;
        float aa = fmaxf(A.z - A.x, 0.0f) * fmaxf(A.w - A.y, 0.0f);
        float ab = fmaxf(B.z - B.x, 0.0f) * fmaxf(B.w - B.y, 0.0f);
        float d = 1.0f - __fdividef(inter, aa + ab - inter + 1e-12f);
        float yr = aw[j] * aw[k];
        float yd = d * 16.0f;
        float wgt = (j == k) ? 1.0f : 2.0f;
        sc2 = wgt * plin2(stab, yr) * plin2(stab + 17, yd);
        float dd = plin2(stab + 51, yr) * plin2(stab + 68, yd);
        dT[j * STR + k] = dd;
        dT[k * STR + j] = dd;
        dC += wgt * fabsf(plin2(stab + 102, yd) - 0.5f);
    }
    __syncwarp();

    // ---- sim (45 strict pairs: lane l; lanes 0-12 also 32+l; lanes 22-31 diag) ----
    const uchar4 pb = g_pairB[l];
    const float2* tb2 = stab + 34;
    float* sP = smP[w];
    {
        float prod = simprod(dT, tb2, pb.x, pb.y, aw[pb.x], aw[pb.y]);
        sP[pb.x * STR + pb.y] = prod;
        sP[pb.y * STR + pb.x] = prod;
    }
    if (l < 13) {
        float prod = simprod(dT, tb2, pb.z, pb.w, aw[pb.z], aw[pb.w]);
        sP[pb.z * STR + pb.w] = prod;
        sP[pb.w * STR + pb.z] = prod;
    } else if (l >= 22) {
        sP[(l - 22) * (STR + 1)] = 1.0f;   // diagonal product == 1 (all diffs identically 0)
    }
    __syncwarp();

    // ---- row_sims reciprocal (lanes 0-9, vectorized) ----
    if (l < OBJ) {
        const float4* rp = (const float4*)(sP + l * STR);
        float4 x0 = rp[0], x1 = rp[1];
        float2 x2 = *(const float2*)(sP + l * STR + 8);
        float s = ((x0.x + x0.y) + (x0.z + x0.w)) + ((x1.x + x1.y) + (x1.z + x1.w)) + (x2.x + x2.y);
        invr[w][l] = __fdividef(1.0f, s);
    }
    __syncwarp();

    // ---- partials: scores / (rj*rk); correction + confs ----
    const float* ivw = invr[w];
    float sT = sc1 * ivw[pa.x] * ivw[pa.y];
    if (l < 23) sT += sc2 * ivw[pa.z] * ivw[pa.w];
    float mC = 0.01f * dC;
    if (l < OBJ) {
        float a4 = aw[l];
        sT += plin2(stab, a4 * a4) * ivw[l];                      // a4^2 = 16*a^2
        mC += 0.1f * fabsf(plin2(stab + 85, a4 * 4.0f) - 0.5f);   // 4*a4 = 16*a
    }

    // ---- butterfly reduction ----
    #pragma unroll
    for (int o = 16; o > 0; o >>= 1) {
        sT += __shfl_xor_sync(0xffffffffu, sT, o);
        mC += __shfl_xor_sync(0xffffffffu, mC, o);
    }
    float total = sqrtf(sT + 1e-20f);
    float conf  = plin2(stab + 119, mC * 16.0f);

    // ---- one_hot * conf, lanes 0-10 ----
    if (act && l < OBJ + 1) {
        float s = fminf(fmaxf(total, 0.0f), (float)OBJ);
        int i = (int)s;
        float f = s - truncf(s);
        int il = i < OBJ ? i : OBJ;
        int ir = (i + 1) < OBJ ? (i + 1) : OBJ;
        float v = (1.0f - f) * (l == il ? 1.0f : 0.0f) + f * (l == ir ? 1.0f : 0.0f);
        out[(size_t)row * (OBJ + 1) + l] = v * conf;
    }
}

extern "C" void kernel_launch(void* const* d_in, const int* in_sizes, int n_in,
                              void* d_out, int out_size) {
    const float* boxes     = (const float*)d_in[0];
    const float* attention = (const float*)d_in[1];
    const float* ws        = (const float*)d_in[2];
    float* out = (float*)d_out;
    int n = in_sizes[1] / MOBJ;
    counter_kernel<<<(n + RPB - 1) / RPB, 256>>>(boxes, attention, ws, out, n);
}

// round 8
// speedup vs baseline: 3.4669x; 1.0580x over previous
#include <cuda_runtime.h>
#include <cuda_bf16.h>
#include <math.h>

#define N_PL 16
#define OBJ  10
#define MOBJ 36
#define RPB  8     // rows (warps) per block
#define STR  12    // padded row stride for 10x10 matrices (48B, 16B-aligned)

// Compile-time pair tables (static .global data; coalesced 128B LDG per warp).
// pairA[l] = (j,k) of 55-pair l  and (j,k) of 55-pair 32+l (lanes 0-22; dc after)
__device__ const uchar4 g_pairA[32] = {
    {0,0,3,8},{0,1,3,9},{0,2,4,4},{0,3,4,5},{0,4,4,6},{0,5,4,7},{0,6,4,8},{0,7,4,9},
    {0,8,5,5},{0,9,5,6},{1,1,5,7},{1,2,5,8},{1,3,5,9},{1,4,6,6},{1,5,6,7},{1,6,6,8},
    {1,7,6,9},{1,8,7,7},{1,9,7,8},{2,2,7,9},{2,3,8,8},{2,4,8,9},{2,5,9,9},{2,6,9,9},
    {2,7,9,9},{2,8,9,9},{2,9,9,9},{3,3,9,9},{3,4,9,9},{3,5,9,9},{3,6,9,9},{3,7,9,9}};
// pairB[l] = (j,k) of 45-pair l  and (j,k) of 45-pair 32+l (lanes 0-12; dc after)
__device__ const uchar4 g_pairB[32] = {
    {0,1,4,7},{0,2,4,8},{0,3,4,9},{0,4,5,6},{0,5,5,7},{0,6,5,8},{0,7,5,9},{0,8,6,7},
    {0,9,6,8},{1,2,6,9},{1,3,7,8},{1,4,7,9},{1,5,8,9},{1,6,8,9},{1,7,8,9},{1,8,8,9},
    {1,9,8,9},{2,3,8,9},{2,4,8,9},{2,5,8,9},{2,6,8,9},{2,7,8,9},{2,8,8,9},{2,9,8,9},
    {3,4,8,9},{3,5,8,9},{3,6,8,9},{3,7,8,9},{3,8,8,9},{3,9,8,9},{4,5,8,9},{4,6,8,9}};

// plin on pre-scaled argument y = 16*x, y in [0,16]; plin = A[i] + y*B[i], i=(int)y
__device__ __forceinline__ float plin2(const float2* __restrict__ tb, float y) {
    int i = (int)y;
    float2 p = tb[i];
    return fmaf(y, p.y, p.x);
}

// product of 10 plin(1-|colj[i]-colk[i]|) terms + att4 term, vectorized column reads
__device__ __forceinline__ float simprod(const float* __restrict__ ddT,
                                         const float2* __restrict__ tb2,
                                         int j, int k, float a4j, float a4k) {
    const float4* cj = (const float4*)(ddT + j * STR);
    const float4* ck = (const float4*)(ddT + k * STR);
    float4 a0 = cj[0], b0 = ck[0];
    float p =  plin2(tb2, fmaf(fabsf(a0.x - b0.x), -16.0f, 16.0f));
    p *= plin2(tb2, fmaf(fabsf(a0.y - b0.y), -16.0f, 16.0f));
    p *= plin2(tb2, fmaf(fabsf(a0.z - b0.z), -16.0f, 16.0f));
    p *= plin2(tb2, fmaf(fabsf(a0.w - b0.w), -16.0f, 16.0f));
    float4 a1 = cj[1], b1 = ck[1];
    p *= plin2(tb2, fmaf(fabsf(a1.x - b1.x), -16.0f, 16.0f));
    p *= plin2(tb2, fmaf(fabsf(a1.y - b1.y), -16.0f, 16.0f));
    p *= plin2(tb2, fmaf(fabsf(a1.z - b1.z), -16.0f, 16.0f));
    p *= plin2(tb2, fmaf(fabsf(a1.w - b1.w), -16.0f, 16.0f));
    float2 a2 = *(const float2*)(ddT + j * STR + 8);
    float2 b2 = *(const float2*)(ddT + k * STR + 8);
    p *= plin2(tb2, fmaf(fabsf(a2.x - b2.x), -16.0f, 16.0f));
    p *= plin2(tb2, fmaf(fabsf(a2.y - b2.y), -16.0f, 16.0f));
    p *= plin2(tb2, fmaf(fabsf(a4j - a4k), -4.0f, 16.0f));   // att stored x4
    return p;
}

__global__ __launch_bounds__(256, 6)
void counter_kernel(const float* __restrict__ boxes,      // [n, 4, 36]
                    const float* __restrict__ attention,  // [n, 36]
                    const float* __restrict__ ws,         // [8, 17]
                    float* __restrict__ out,              // [n, 11]
                    int n) {
    __shared__ float4 tabRel[N_PL + 1];    // (A0,B0,A3,B3) keyed by yr
    __shared__ float4 tabDist[N_PL + 1];   // (A1,B1,A4,B4) keyed by yd
    __shared__ float2 tab2[N_PL + 1];
    __shared__ float2 tab5[N_PL + 1];
    __shared__ float2 tab6[N_PL + 1];      // keyed by yd (index reused)
    __shared__ float2 tab7[N_PL + 1];
    __shared__ uint4  karr[RPB][9];        // 36 sortable 32-bit keys per row
    __shared__ float  att[RPB][OBJ];       // holds 4*sigmoid
    __shared__ float4 boxs[RPB][OBJ];
    __shared__ float  ddT[RPB][OBJ * STR];
    __shared__ float  smP[RPB][OBJ * STR];
    __shared__ float  invr[RPB][OBJ];

    const int t = threadIdx.x;
    const int w = t >> 5, l = t & 31;
    const int row = blockIdx.x * RPB + w;
    const bool act = row < n;

    // ---- plin table w built by warp w: |ws|, shfl inclusive scan, normalize ----
    {
        float wv0 = (l <= N_PL) ? fabsf(ws[w * 17 + l]) : 0.0f;
        float cs = wv0;
        #pragma unroll
        for (int o = 1; o <= 16; o <<= 1) {
            float up = __shfl_up_sync(0xffffffffu, cs, o);
            if (l >= o) cs += up;
        }
        float totalw = __shfl_sync(0xffffffffu, cs, N_PL);
        float inv = __fdividef(1.0f, totalw);
        float wnext = __shfl_down_sync(0xffffffffu, wv0, 1);
        float B = (l < N_PL) ? wnext * inv : 0.0f;
        float A = fmaf(-(float)l, B, cs * inv);
        if (l <= N_PL) {
            if      (w == 0) { ((float*)tabRel)[4*l]   = A; ((float*)tabRel)[4*l+1]  = B; }
            else if (w == 3) { ((float*)tabRel)[4*l+2] = A; ((float*)tabRel)[4*l+3]  = B; }
            else if (w == 1) { ((float*)tabDist)[4*l]  = A; ((float*)tabDist)[4*l+1] = B; }
            else if (w == 4) { ((float*)tabDist)[4*l+2]= A; ((float*)tabDist)[4*l+3] = B; }
            else if (w == 2) tab2[l] = make_float2(A, B);
            else if (w == 5) tab5[l] = make_float2(A, B);
            else if (w == 6) tab6[l] = make_float2(A, B);
            else             tab7[l] = make_float2(A, B);
        }
    }

    // ---- load attention, build monotone 32-bit sortable keys ----
    float v1 = 0.0f, v2 = 0.0f;
    if (act) {
        v1 = attention[(size_t)row * MOBJ + l];
        if (l < 4) v2 = attention[(size_t)row * MOBJ + 32 + l];
    }
    unsigned u1 = __float_as_uint(v1);
    unsigned kv1 = (u1 & 0x80000000u) ? ~u1 : (u1 | 0x80000000u);
    ((unsigned*)karr[w])[l] = kv1;
    unsigned u2 = __float_as_uint(v2);
    unsigned kv2 = (u2 & 0x80000000u) ? ~u2 : (u2 | 0x80000000u);
    if (l < 4) ((unsigned*)karr[w])[32 + l] = kv2;
    __syncthreads();   // the ONLY block barrier: tables (cross-warp) + own keys

    // ---- rank among all 36 via strict > (keys unique: continuous input data) ----
    int r1 = 0;
    const uint4* kp = karr[w];
    #pragma unroll
    for (int p = 0; p < 9; p++) {
        uint4 kk = kp[p];
        r1 += (kk.x > kv1) + (kk.y > kv1) + (kk.z > kv1) + (kk.w > kv1);
    }
    uint4 ex = kp[8];   // keys 32..35

    // ---- ranks of the 4 extras via ballots ----
    unsigned b0 = __ballot_sync(0xffffffffu, kv1 > ex.x);
    unsigned b1 = __ballot_sync(0xffffffffu, kv1 > ex.y);
    unsigned b2 = __ballot_sync(0xffffffffu, kv1 > ex.z);
    unsigned b3 = __ballot_sync(0xffffffffu, kv1 > ex.w);
    int r2 = (l == 0) ? __popc(b0) : (l == 1) ? __popc(b1) : (l == 2) ? __popc(b2) : __popc(b3);
    r2 += (ex.x > kv2) + (ex.y > kv2) + (ex.z > kv2) + (ex.w > kv2);

    // ---- gather selected objects (att stored as 4*sigmoid) ----
    if (act && r1 < OBJ) {
        att[w][r1] = __fdividef(4.0f, 1.0f + __expf(-v1));
        const float* bp = boxes + (size_t)row * (4 * MOBJ) + l;
        boxs[w][r1] = make_float4(bp[0], bp[MOBJ], bp[2 * MOBJ], bp[3 * MOBJ]);
    }
    if (act && l < 4 && r2 < OBJ) {
        att[w][r2] = __fdividef(4.0f, 1.0f + __expf(-v2));
        const float* bp = boxes + (size_t)row * (4 * MOBJ) + 32 + l;
        boxs[w][r2] = make_float4(bp[0], bp[MOBJ], bp[2 * MOBJ], bp[3 * MOBJ]);
    }
    __syncwarp();

    // ---- pairwise (55 pairs: lane l; lanes 0-22 also pair 32+l) ----
    const uchar4 pa = g_pairA[l];
    const float* aw = att[w];
    float* dT = ddT[w];
    float dC, sc1, sc2 = 0.0f;
    {
        const int j = pa.x, k = pa.y;
        float4 A = boxs[w][j], B = boxs[w][k];
        float iw = fmaxf(fminf(A.z, B.z) - fmaxf(A.x, B.x), 0.0f);
        float ih = fmaxf(fminf(A.w, B.w) - fmaxf(A.y, B.y), 0.0f);
        float inter = iw * ih;
        float aa = fmaxf(A.z - A.x, 0.0f) * fmaxf(A.w - A.y, 0.0f);
        float ab = fmaxf(B.z - B.x, 0.0f) * fmaxf(B.w - B.y, 0.0f);
        float d = 1.0f - __fdividef(inter, aa + ab - inter + 1e-12f);
        float yr = aw[j] * aw[k];          // (4a)(4a) = 16*rel
        float yd = d * 16.0f;
        float wgt = (j == k) ? 1.0f : 2.0f;
        float4 pr = tabRel[(int)yr];
        float4 pd = tabDist[(int)yd];
        float2 p6 = tab6[(int)yd];
        sc1 = wgt * fmaf(yr, pr.y, pr.x) * fmaf(yd, pd.y, pd.x);
        float dd = fmaf(yr, pr.w, pr.z) * fmaf(yd, pd.w, pd.z);
        dT[j * STR + k] = dd;
        dT[k * STR + j] = dd;
        dC = wgt * fabsf(fmaf(yd, p6.y, p6.x) - 0.5f);
    }
    if (l < 23) {
        const int j = pa.z, k = pa.w;
        float4 A = boxs[w][j], B = boxs[w][k];
        float iw = fmaxf(fminf(A.z, B.z) - fmaxf(A.x, B.x), 0.0f);
        float ih = fmaxf(fminf(A.w, B.w) - fmaxf(A.y, B.y), 0.0f);
        float inter = iw * ih;
        float aa = fmaxf(A.z - A.x, 0.0f) * fmaxf(A.w - A.y, 0.0f);
        float ab = fmaxf(B.z - B.x, 0.0f) * fmaxf(B.w - B.y, 0.0f);
        float d = 1.0f - __fdividef(inter, aa + ab - inter + 1e-12f);
        float yr = aw[j] * aw[k];
        float yd = d * 16.0f;
        float wgt = (j == k) ? 1.0f : 2.0f;
        float4 pr = tabRel[(int)yr];
        float4 pd = tabDist[(int)yd];
        float2 p6 = tab6[(int)yd];
        sc2 = wgt * fmaf(yr, pr.y, pr.x) * fmaf(yd, pd.y, pd.x);
        float dd = fmaf(yr, pr.w, pr.z) * fmaf(yd, pd.w, pd.z);
        dT[j * STR + k] = dd;
        dT[k * STR + j] = dd;
        dC += wgt * fabsf(fmaf(yd, p6.y, p6.x) - 0.5f);
    }
    __syncwarp();

    // ---- sim (45 strict pairs: lane l; lanes 0-12 also 32+l; lanes 22-31 diag) ----
    const uchar4 pb = g_pairB[l];
    float* sP = smP[w];
    {
        float prod = simprod(dT, tab2, pb.x, pb.y, aw[pb.x], aw[pb.y]);
        sP[pb.x * STR + pb.y] = prod;
        sP[pb.y * STR + pb.x] = prod;
    }
    if (l < 13) {
        float prod = simprod(dT, tab2, pb.z, pb.w, aw[pb.z], aw[pb.w]);
        sP[pb.z * STR + pb.w] = prod;
        sP[pb.w * STR + pb.z] = prod;
    } else if (l >= 22) {
        sP[(l - 22) * (STR + 1)] = 1.0f;   // diagonal product == 1 (all diffs identically 0)
    }
    __syncwarp();

    // ---- row_sims reciprocal (lanes 0-9, vectorized) ----
    if (l < OBJ) {
        const float4* rp = (const float4*)(sP + l * STR);
        float4 x0 = rp[0], x1 = rp[1];
        float2 x2 = *(const float2*)(sP + l * STR + 8);
        float s = ((x0.x + x0.y) + (x0.z + x0.w)) + ((x1.x + x1.y) + (x1.z + x1.w)) + (x2.x + x2.y);
        invr[w][l] = __fdividef(1.0f, s);
    }
    __syncwarp();

    // ---- partials: scores / (rj*rk); correction + confs ----
    const float* ivw = invr[w];
    float sT = sc1 * ivw[pa.x] * ivw[pa.y];
    if (l < 23) sT += sc2 * ivw[pa.z] * ivw[pa.w];
    float mC = 0.01f * dC;
    if (l < OBJ) {
        float a4 = aw[l];
        float ya = a4 * a4;                        // 16 * a^2
        float4 pr = tabRel[(int)ya];
        sT += fmaf(ya, pr.y, pr.x) * ivw[l];
        mC += 0.1f * fabsf(plin2(tab5, a4 * 4.0f) - 0.5f);
    }

    // ---- butterfly reduction ----
    #pragma unroll
    for (int o = 16; o > 0; o >>= 1) {
        sT += __shfl_xor_sync(0xffffffffu, sT, o);
        mC += __shfl_xor_sync(0xffffffffu, mC, o);
    }
    float total = sqrtf(sT + 1e-20f);
    float conf  = plin2(tab7, mC * 16.0f);

    // ---- one_hot * conf, lanes 0-10 ----
    if (act && l < OBJ + 1) {
        float s = fminf(fmaxf(total, 0.0f), (float)OBJ);
        int i = (int)s;
        float f = s - truncf(s);
        int il = i < OBJ ? i : OBJ;
        int ir = (i + 1) < OBJ ? (i + 1) : OBJ;
        float v = (1.0f - f) * (l == il ? 1.0f : 0.0f) + f * (l == ir ? 1.0f : 0.0f);
        out[(size_t)row * (OBJ + 1) + l] = v * conf;
    }
}

extern "C" void kernel_launch(void* const* d_in, const int* in_sizes, int n_in,
                              void* d_out, int out_size) {
    const float* boxes     = (const float*)d_in[0];
    const float* attention = (const float*)d_in[1];
    const float* ws        = (const float*)d_in[2];
    float* out = (float*)d_out;
    int n = in_sizes[1] / MOBJ;
    counter_kernel<<<(n + RPB - 1) / RPB, 256>>>(boxes, attention, ws, out, n);
}